// round 8
// baseline (speedup 1.0000x reference)
#include <cuda_runtime.h>
#include <cuda_bf16.h>
#include <cstdint>
#include <math.h>

#define QN 16
#define IN 64
#define PB 128
#define JN 256
#define DN 768

#define NSLAB 24               // 768 / 32 bf16 per slab
#define A_STAGE 4096           // 64 rows x 64B
#define B_STAGE 16384          // 256 rows x 64B
#define STAGE_BYTES (A_STAGE + B_STAGE)   // 20480
#define NSTAGE 4
#define DYN_SMEM (NSTAGE * STAGE_BYTES)   // 81920

// Scratch (device globals: no allocation)
__device__ __nv_bfloat16 g_qbf[QN * IN * DN];    // 1.5 MB normalized q, bf16
__device__ __nv_bfloat16 g_pbf[PB * JN * DN];    // 48 MB normalized p, bf16
__device__ float g_scores[QN * PB];
__device__ float g_mv[QN * PB];

// ---------------------------------------------------------------------------
// Helpers
// ---------------------------------------------------------------------------
static __device__ __forceinline__ uint32_t smem_u32(const void* p) {
    uint32_t a;
    asm("{ .reg .u64 t; cvta.to.shared.u64 t, %1; cvt.u32.u64 %0, t; }"
        : "=r"(a) : "l"(p));
    return a;
}

// 64B-row swizzle: rows packed in pairs per 128B line.
// chunk c in [0,4), row r. offset = (r>>1)*128 + (((c + 4*(r&1)) ^ ((r>>1)&7)) << 4)
static __device__ __forceinline__ uint32_t swz64(int r, int c) {
    return (uint32_t)((r >> 1) * 128 + ((((c + ((r & 1) << 2))) ^ ((r >> 1) & 7)) << 4));
}

static __device__ __forceinline__ void cpasync16(uint32_t saddr, const void* g) {
    asm volatile("cp.async.cg.shared.global [%0], [%1], 16;" :: "r"(saddr), "l"(g) : "memory");
}

static __device__ __forceinline__ void ldmx4(uint32_t* r, uint32_t addr) {
    asm volatile("ldmatrix.sync.aligned.m8n8.x4.shared.b16 {%0,%1,%2,%3}, [%4];"
                 : "=r"(r[0]), "=r"(r[1]), "=r"(r[2]), "=r"(r[3]) : "r"(addr));
}

static __device__ __forceinline__ void mma_bf16(float* c, const uint32_t* a,
                                                uint32_t b0, uint32_t b1) {
    asm volatile(
        "mma.sync.aligned.m16n8k16.row.col.f32.bf16.bf16.f32 "
        "{%0,%1,%2,%3}, {%4,%5,%6,%7}, {%8,%9}, {%0,%1,%2,%3};"
        : "+f"(c[0]), "+f"(c[1]), "+f"(c[2]), "+f"(c[3])
        : "r"(a[0]), "r"(a[1]), "r"(a[2]), "r"(a[3]), "r"(b0), "r"(b1));
}

// ---------------------------------------------------------------------------
// Normalize + convert to bf16 (q and p fused in one launch).
// One block (192 threads) per row of 768.
// ---------------------------------------------------------------------------
static __device__ __forceinline__ void norm_convert_row(const float* __restrict__ xr,
                                                        __nv_bfloat162* __restrict__ yr) {
    int t = threadIdx.x;  // 192
    float4 v = ((const float4*)xr)[t];
    float ss = v.x * v.x + v.y * v.y + v.z * v.z + v.w * v.w;
#pragma unroll
    for (int o = 16; o; o >>= 1) ss += __shfl_xor_sync(0xffffffffu, ss, o);
    __shared__ float red[6];
    if ((t & 31) == 0) red[t >> 5] = ss;
    __syncthreads();
    float tot = 0.f;
#pragma unroll
    for (int i = 0; i < 6; i++) tot += red[i];
    float inv = 1.0f / fmaxf(sqrtf(tot), 1e-12f);
    yr[2 * t + 0] = __floats2bfloat162_rn(v.x * inv, v.y * inv);
    yr[2 * t + 1] = __floats2bfloat162_rn(v.z * inv, v.w * inv);
}

__global__ void norm_all_kernel(const float* __restrict__ qh,
                                const float* __restrict__ ph) {
    size_t b = blockIdx.x;
    if (b < QN * IN)
        norm_convert_row(qh + b * DN, (__nv_bfloat162*)(g_qbf + b * DN));
    else {
        size_t row = b - QN * IN;
        norm_convert_row(ph + row * DN, (__nv_bfloat162*)(g_pbf + row * DN));
    }
}

// ---------------------------------------------------------------------------
// scores[q][p] = dot(q_hidden[q,0,:], p_hidden[p,0,:])  fp32, warp per pair
// ---------------------------------------------------------------------------
__global__ void scores_kernel(const float* __restrict__ qh,
                              const float* __restrict__ ph) {
    int p = blockIdx.x;
    int q = threadIdx.x >> 5;
    int lane = threadIdx.x & 31;
    const float* qr = qh + (size_t)q * IN * DN;
    const float* pr = ph + (size_t)p * JN * DN;
    float s = 0.f;
#pragma unroll
    for (int i = 0; i < DN / 32; i++) s = fmaf(qr[lane + 32 * i], pr[lane + 32 * i], s);
#pragma unroll
    for (int o = 16; o; o >>= 1) s += __shfl_xor_sync(0xffffffffu, s, o);
    if (lane == 0) g_scores[q * PB + p] = s;
}

// ---------------------------------------------------------------------------
// mv GEMM via bf16 mma.sync m16n8k16 on pre-normalized bf16 data.
// Grid (p=128, q=16). CTA tile 64(i) x 256(j), K=768 in 24 slabs of 32.
// 8 warps = 2(m) x 4(n); warp tile 32x64 = 2(mt) x 8(nt) fragments.
// 4-stage cp.async pipeline (wait_group 2), 1 sync/slab, 2 CTAs/SM.
// ---------------------------------------------------------------------------
static __device__ __forceinline__ void load_slab(uint32_t stage_base, int mb, int p,
                                                 int k0, int tid) {
    // A: 64 rows x 32 bf16 (64B) = 256 x 16B chunks, 1 per thread
    {
        int r = tid >> 2, c = tid & 3;
        const __nv_bfloat16* g = g_qbf + (size_t)(mb * 64 + r) * DN + k0 + c * 8;
        cpasync16(stage_base + swz64(r, c), g);
    }
    // B: 256 rows x 32 bf16 = 1024 x 16B chunks, 4 per thread
    uint32_t bbase = stage_base + A_STAGE;
#pragma unroll
    for (int i = 0; i < 4; i++) {
        int idx = tid + 256 * i;
        int r = idx >> 2, c = idx & 3;
        const __nv_bfloat16* g = g_pbf + (size_t)(p * 256 + r) * DN + k0 + c * 8;
        cpasync16(bbase + swz64(r, c), g);
    }
}

__global__ __launch_bounds__(256, 2) void mv_tc_kernel() {
    extern __shared__ __align__(128) char dynraw[];
    __shared__ float s_wmax[8];

    const int tid = threadIdx.x;
    const int p = blockIdx.x;
    const int mb = blockIdx.y;  // q row (64 i's per q)
    const int w = tid >> 5, lane = tid & 31;
    const int wm = w >> 2, wn = w & 3;

    const uint32_t dynbase = smem_u32(dynraw);

    // --- precomputed ldmatrix addresses (offsets within a stage) ---
    // A frag (m16n8k16 x4): lane sel
    const int selA = lane >> 3;
    const int arow_l = (lane & 7) + ((selA & 1) << 3);  // row within 16
    const int ah = selA >> 1;                           // k8-half: chunk = 2*kk + ah
    uint32_t aAddr[2][2];                               // [mt][kk]
#pragma unroll
    for (int mt = 0; mt < 2; mt++) {
        int r = wm * 32 + mt * 16 + arow_l;
#pragma unroll
        for (int kk = 0; kk < 2; kk++)
            aAddr[mt][kk] = swz64(r, 2 * kk + ah);
    }
    // B frag (x4 = two n8 tiles)
    const int jrow_l = (lane & 7) + ((lane >> 4) << 3);
    const int bh = (lane >> 3) & 1;
    uint32_t bAddr[4][2];                               // [np][kk]
#pragma unroll
    for (int np = 0; np < 4; np++) {
        int r = wn * 64 + np * 16 + jrow_l;
#pragma unroll
        for (int kk = 0; kk < 2; kk++)
            bAddr[np][kk] = A_STAGE + swz64(r, 2 * kk + bh);
    }

    float acc[2][8][4];
#pragma unroll
    for (int mt = 0; mt < 2; mt++)
#pragma unroll
        for (int nt = 0; nt < 8; nt++)
#pragma unroll
            for (int c = 0; c < 4; c++) acc[mt][nt][c] = 0.f;

    // Prologue: fill 3 of 4 stages
#pragma unroll
    for (int pre = 0; pre < 3; pre++) {
        load_slab(dynbase + pre * STAGE_BYTES, mb, p, pre * 32, tid);
        asm volatile("cp.async.commit_group;" ::: "memory");
    }

    for (int s = 0; s < NSLAB; s++) {
        asm volatile("cp.async.wait_group 2;" ::: "memory");
        __syncthreads();

        const uint32_t Sb = dynbase + (s & 3) * STAGE_BYTES;

#pragma unroll
        for (int kk = 0; kk < 2; kk++) {
            uint32_t a[2][4];
            ldmx4(a[0], Sb + aAddr[0][kk]);
            ldmx4(a[1], Sb + aAddr[1][kk]);
#pragma unroll
            for (int np = 0; np < 4; np++) {
                uint32_t b[4];
                ldmx4(b, Sb + bAddr[np][kk]);
                mma_bf16(acc[0][np * 2 + 0], a[0], b[0], b[1]);
                mma_bf16(acc[1][np * 2 + 0], a[1], b[0], b[1]);
                mma_bf16(acc[0][np * 2 + 1], a[0], b[2], b[3]);
                mma_bf16(acc[1][np * 2 + 1], a[1], b[2], b[3]);
            }
        }

        if (s + 3 < NSLAB) {
            load_slab(dynbase + ((s + 3) & 3) * STAGE_BYTES, mb, p, (s + 3) * 32, tid);
            asm volatile("cp.async.commit_group;" ::: "memory");
        } else {
            asm volatile("cp.async.commit_group;" ::: "memory");  // keep group count in step
        }
    }

    // Epilogue: pure max (operands pre-normalized)
    float mx = -INFINITY;
#pragma unroll
    for (int mt = 0; mt < 2; mt++)
#pragma unroll
        for (int nt = 0; nt < 8; nt++)
#pragma unroll
            for (int c = 0; c < 4; c++) mx = fmaxf(mx, acc[mt][nt][c]);
#pragma unroll
    for (int o = 16; o; o >>= 1) mx = fmaxf(mx, __shfl_xor_sync(0xffffffffu, mx, o));
    if (lane == 0) s_wmax[w] = mx;
    __syncthreads();
    if (tid == 0) {
        float m = s_wmax[0];
#pragma unroll
        for (int i = 1; i < 8; i++) m = fmaxf(m, s_wmax[i]);
        g_mv[mb * PB + p] = m;
    }
}

// ---------------------------------------------------------------------------
// Final loss (unchanged logic)
// ---------------------------------------------------------------------------
__global__ void loss_kernel(float* __restrict__ out) {
    int tid = threadIdx.x;  // 512
    int w = tid >> 5;
    int lane = tid & 31;
    const float* sr = g_scores + w * PB;
    const float* mr = g_mv + w * PB;
    float s[4], m[4], si[4];
#pragma unroll
    for (int c = 0; c < 4; c++) {
        int j = lane + 32 * c;
        s[c] = sr[j];
        m[c] = mr[j];
        si[c] = s[c] + 0.3f * m[c];
    }
    float mxs = -INFINITY, mxm = -INFINITY, mxi = -INFINITY;
#pragma unroll
    for (int c = 0; c < 4; c++) {
        mxs = fmaxf(mxs, s[c]);
        mxm = fmaxf(mxm, m[c]);
        mxi = fmaxf(mxi, si[c]);
    }
#pragma unroll
    for (int o = 16; o; o >>= 1) {
        mxs = fmaxf(mxs, __shfl_xor_sync(0xffffffffu, mxs, o));
        mxm = fmaxf(mxm, __shfl_xor_sync(0xffffffffu, mxm, o));
        mxi = fmaxf(mxi, __shfl_xor_sync(0xffffffffu, mxi, o));
    }
    float es = 0.f, em = 0.f, ei = 0.f;
#pragma unroll
    for (int c = 0; c < 4; c++) {
        es += expf(s[c] - mxs);
        em += expf(m[c] - mxm);
        ei += expf(si[c] - mxi);
    }
#pragma unroll
    for (int o = 16; o; o >>= 1) {
        es += __shfl_xor_sync(0xffffffffu, es, o);
        em += __shfl_xor_sync(0xffffffffu, em, o);
        ei += __shfl_xor_sync(0xffffffffu, ei, o);
    }
    float lse_s = mxs + logf(es);
    float lse_m = mxm + logf(em);
    float lse_i = mxi + logf(ei);

    float k1 = 0.f, k2 = 0.f;
#pragma unroll
    for (int c = 0; c < 4; c++) {
        float t = si[c] - lse_i;
        float pb = expf(t);
        k1 += pb * (t - (s[c] - lse_s));
        k2 += pb * (t - (m[c] - lse_m));
    }
#pragma unroll
    for (int o = 16; o; o >>= 1) {
        k1 += __shfl_xor_sync(0xffffffffu, k1, o);
        k2 += __shfl_xor_sync(0xffffffffu, k2, o);
    }

    __shared__ float sm[16][4];
    if (lane == 0) {
        int tgt = w * 8;
        sm[w][0] = lse_s - sr[tgt];
        sm[w][1] = lse_i - (sr[tgt] + 0.3f * mr[tgt]);
        sm[w][2] = k1;
        sm[w][3] = k2;
    }
    __syncthreads();
    if (tid == 0) {
        float ce_s = 0.f, ce_i = 0.f, k1s = 0.f, k2s = 0.f;
#pragma unroll
        for (int i = 0; i < 16; i++) {
            ce_s += sm[i][0];
            ce_i += sm[i][1];
            k1s += sm[i][2];
            k2s += sm[i][3];
        }
        ce_s *= (1.0f / 16.0f);
        ce_i *= (1.0f / 16.0f);
        k1s *= (1.0f / 16.0f);
        k2s *= (1.0f / 16.0f);
        float L1 = 0.3f * (ce_s + k2s + ce_i);
        float L2 = 0.2f * (k1s + k2s);
        out[0] = 0.5f * (L1 + L2);
    }
}

// ---------------------------------------------------------------------------
extern "C" void kernel_launch(void* const* d_in, const int* in_sizes, int n_in,
                              void* d_out, int out_size) {
    const float* qh = (const float*)d_in[0];
    const float* ph = (const float*)d_in[1];
    if (n_in >= 2 && in_sizes[0] > in_sizes[1]) {
        const float* t = qh; qh = ph; ph = t;
    }

    cudaFuncSetAttribute(mv_tc_kernel, cudaFuncAttributeMaxDynamicSharedMemorySize,
                         DYN_SMEM);

    scores_kernel<<<PB, 512>>>(qh, ph);
    norm_all_kernel<<<QN * IN + PB * JN, 192>>>(qh, ph);
    mv_tc_kernel<<<dim3(PB, QN), 256, DYN_SMEM>>>();
    loss_kernel<<<1, 512>>>((float*)d_out);
}